// round 16
// baseline (speedup 1.0000x reference)
#include <cuda_runtime.h>
#include <cuda_fp16.h>
#include <cstdint>
#include <math.h>

#define B_ 2
#define S_ 2048
#define D_ 1024
#define H_ 16
#define DK_ 64
#define NTOK (B_*S_)

// ---------------------------------------------------------------------------
// Scratch (device globals — allocation is forbidden)
// ---------------------------------------------------------------------------
__device__ __half g_qf[(size_t)NTOK * D_];
__device__ __half g_kf[(size_t)NTOK * D_];
__device__ __half g_vf[(size_t)NTOK * D_];
__device__ __half g_wq[(size_t)D_ * D_];
__device__ __half g_wk[(size_t)D_ * D_];
__device__ __half g_wv[(size_t)D_ * D_];
__device__ __half g_wo[(size_t)D_ * D_];
__device__ __half g_Qh[(size_t)NTOK * D_];   // [B,H,S,DK]
__device__ __half g_Kh[(size_t)NTOK * D_];   // [B,H,S,DK]
__device__ __half g_Vh[(size_t)NTOK * D_];   // [B,H,S,DK]
__device__ __half g_Xf[(size_t)NTOK * D_];   // [B,S,D]
__device__ int    g_maskAll;

// ---------------------------------------------------------------------------
// Baseline-PTX helpers (no sm_103a-only features)
// ---------------------------------------------------------------------------
__device__ __forceinline__ uint32_t smem_u32(const void* p) {
    uint32_t a;
    asm("{ .reg .u64 t; cvta.to.shared.u64 t, %1; cvt.u32.u64 %0, t; }"
        : "=r"(a) : "l"(p));
    return a;
}

#define CPA(dst, src) \
    asm volatile("cp.async.cg.shared.global [%0], [%1], 16;" \
        :: "r"((uint32_t)(dst)), "l"(src) : "memory")
#define CPC() asm volatile("cp.async.commit_group;" ::: "memory")
#define CPW(N) asm volatile("cp.async.wait_group %0;" :: "n"(N) : "memory")

__device__ __forceinline__ void ldsm4(uint32_t* r, uint32_t a) {
    asm volatile("ldmatrix.sync.aligned.m8n8.x4.shared.b16 {%0,%1,%2,%3}, [%4];"
        : "=r"(r[0]), "=r"(r[1]), "=r"(r[2]), "=r"(r[3]) : "r"(a));
}
__device__ __forceinline__ void ldsm4t(uint32_t* r, uint32_t a) {
    asm volatile("ldmatrix.sync.aligned.m8n8.x4.trans.shared.b16 {%0,%1,%2,%3}, [%4];"
        : "=r"(r[0]), "=r"(r[1]), "=r"(r[2]), "=r"(r[3]) : "r"(a));
}
__device__ __forceinline__ void mma16816(float* d, const uint32_t* a, const uint32_t* b) {
    asm volatile("mma.sync.aligned.m16n8k16.row.col.f32.f16.f16.f32 "
        "{%0,%1,%2,%3}, {%4,%5,%6,%7}, {%8,%9}, {%0,%1,%2,%3};"
        : "+f"(d[0]), "+f"(d[1]), "+f"(d[2]), "+f"(d[3])
        : "r"(a[0]), "r"(a[1]), "r"(a[2]), "r"(a[3]), "r"(b[0]), "r"(b[1]));
}

// exp (f32) pair -> packed f16x2; also accumulates e0+e1 into *sum
__device__ __forceinline__ uint32_t exp_pack_sum(float lo, float hi, float* sum) {
    float e0 = __expf(lo), e1 = __expf(hi);
    *sum += e0 + e1;
    uint32_t u;
    asm("cvt.rn.f16x2.f32 %0, %1, %2;" : "=r"(u) : "f"(e1), "f"(e0));
    return u;
}

// swizzle: 128B rows (8 x 16B chunks)
__device__ __forceinline__ uint32_t sw128(int r, int ch) {
    return (uint32_t)(r * 128 + 16 * (ch ^ (r & 7)));
}

// ---------------------------------------------------------------------------
// fused fp32 -> fp16 conversions (grid.y selects tensor; 8 elems/thread)
// also re-arms g_maskAll (stream-ordered before the mask reduce slice)
// ---------------------------------------------------------------------------
__global__ void __launch_bounds__(256) cvtA_kernel(
    const float* __restrict__ a0, const float* __restrict__ a1,
    const float* __restrict__ a2,
    __half* __restrict__ o0, __half* __restrict__ o1, __half* __restrict__ o2)
{
    if (blockIdx.x == 0 && blockIdx.y == 0 && threadIdx.x == 0) g_maskAll = 1;
    const int z = blockIdx.y;
    const float* in = (z == 0) ? a0 : (z == 1) ? a1 : a2;
    __half* out = (z == 0) ? o0 : (z == 1) ? o1 : o2;
    int i = (blockIdx.x * 256 + threadIdx.x) * 8;
    float4 va = *(const float4*)(in + i);
    float4 vb = *(const float4*)(in + i + 4);
    __half2 h0 = __floats2half2_rn(va.x, va.y);
    __half2 h1 = __floats2half2_rn(va.z, va.w);
    __half2 h2 = __floats2half2_rn(vb.x, vb.y);
    __half2 h3 = __floats2half2_rn(vb.z, vb.w);
    uint4 u;
    u.x = *(uint32_t*)&h0; u.y = *(uint32_t*)&h1;
    u.z = *(uint32_t*)&h2; u.w = *(uint32_t*)&h3;
    *(uint4*)(out + i) = u;
}

__global__ void __launch_bounds__(256) cvtW_kernel(
    const float* __restrict__ a0, const float* __restrict__ a1,
    const float* __restrict__ a2, const float* __restrict__ a3,
    __half* __restrict__ o0, __half* __restrict__ o1,
    __half* __restrict__ o2, __half* __restrict__ o3)
{
    const int z = blockIdx.y;
    const float* in = (z == 0) ? a0 : (z == 1) ? a1 : (z == 2) ? a2 : a3;
    __half* out = (z == 0) ? o0 : (z == 1) ? o1 : (z == 2) ? o2 : o3;
    int i = (blockIdx.x * 256 + threadIdx.x) * 8;
    float4 va = *(const float4*)(in + i);
    float4 vb = *(const float4*)(in + i + 4);
    __half2 h0 = __floats2half2_rn(va.x, va.y);
    __half2 h1 = __floats2half2_rn(va.z, va.w);
    __half2 h2 = __floats2half2_rn(vb.x, vb.y);
    __half2 h3 = __floats2half2_rn(vb.z, vb.w);
    uint4 u;
    u.x = *(uint32_t*)&h0; u.y = *(uint32_t*)&h1;
    u.z = *(uint32_t*)&h2; u.w = *(uint32_t*)&h3;
    *(uint4*)(out + i) = u;
}

// ---------------------------------------------------------------------------
// HMMA GEMM body: C[m,n] = sum_k A[m,k]*W[n,k] + bias[n]
// CTA tile 128x128, 256 thr = 8 warps (2m x 4n), warp tile 64x32, k-chunk 64.
// 3-stage cp.async pipeline (3 x 32KB = 96KB DYNAMIC smem), 1 barrier/iter.
// EPI: 0 = f16 scattered to [B,H,S,DK]; 2 = f32 flat [M,D]
// ---------------------------------------------------------------------------
template<int EPI>
__device__ __forceinline__ void gemm_body(
    const __half* __restrict__ A, const __half* __restrict__ W,
    const float* __restrict__ bias, void* __restrict__ outp,
    char* smem, int m0, int n0)
{
    const uint32_t sb = smem_u32(smem);
    const int tid = threadIdx.x, wid = tid >> 5, lane = tid & 31;
    const int gid = lane >> 2, tig = lane & 3;
    const int wm = wid >> 2, wn = wid & 3;

    // staging: 128 rows x 128B per operand per stage; 4 chunks/thread/operand
    auto stage = [&](int kc, int reg) {
        const uint32_t base = sb + reg * 32768;
        #pragma unroll
        for (int i = 0; i < 4; i++) {
            int idx = tid + i * 256;           // 0..1023
            int r = idx >> 3, ch = idx & 7;
            CPA(base + sw128(r, ch),
                A + (size_t)(m0 + r) * D_ + kc * 64 + ch * 8);
            CPA(base + 16384 + sw128(r, ch),
                W + (size_t)(n0 + r) * D_ + kc * 64 + ch * 8);
        }
        CPC();
    };

    stage(0, 0);
    stage(1, 1);
    float acc[4][4][4] = {};

    for (int kc = 0; kc < 16; ++kc) {
        if (kc < 15) { CPW(1); } else { CPW(0); }
        __syncthreads();
        if (kc + 2 < 16) stage(kc + 2, (kc + 2) % 3);
        const uint32_t base = sb + (kc % 3) * 32768;

        #pragma unroll
        for (int kt = 0; kt < 4; ++kt) {
            uint32_t af[4][4];
            #pragma unroll
            for (int mt = 0; mt < 4; mt++) {
                int r = wm * 64 + mt * 16 + (lane & 7) + ((lane >> 3) & 1) * 8;
                int ch = kt * 2 + (lane >> 4);
                ldsm4(af[mt], base + sw128(r, ch));
            }
            uint32_t bf[4][2];
            #pragma unroll
            for (int p = 0; p < 2; p++) {
                int r = wn * 32 + p * 16 + (lane & 7) + ((lane >> 4) & 1) * 8;
                int ch = kt * 2 + ((lane >> 3) & 1);
                uint32_t t[4];
                ldsm4(t, base + 16384 + sw128(r, ch));
                bf[p * 2][0] = t[0]; bf[p * 2][1] = t[1];
                bf[p * 2 + 1][0] = t[2]; bf[p * 2 + 1][1] = t[3];
            }
            #pragma unroll
            for (int mt = 0; mt < 4; mt++)
                #pragma unroll
                for (int nt = 0; nt < 4; nt++)
                    mma16816(acc[mt][nt], af[mt], bf[nt]);
        }
    }

    // epilogue
    #pragma unroll
    for (int mt = 0; mt < 4; mt++) {
        #pragma unroll
        for (int nt = 0; nt < 4; nt++) {
            const int row0 = m0 + wm * 64 + mt * 16 + gid;
            const int col  = n0 + wn * 32 + nt * 8 + 2 * tig;
            const float b0 = __ldg(bias + col), b1 = __ldg(bias + col + 1);
            const float v0 = acc[mt][nt][0] + b0, v1 = acc[mt][nt][1] + b1;
            const float v2 = acc[mt][nt][2] + b0, v3 = acc[mt][nt][3] + b1;
            if (EPI == 2) {
                float* out = (float*)outp;
                *(float2*)(out + (size_t)row0 * D_ + col)       = make_float2(v0, v1);
                *(float2*)(out + (size_t)(row0 + 8) * D_ + col) = make_float2(v2, v3);
            } else {
                __half* out = (__half*)outp;
                const int bi = row0 >> 11, s = row0 & (S_ - 1);
                const int hh = col >> 6, dk = col & 63;
                __half2* p0 = (__half2*)(out + ((size_t)(bi * H_ + hh) * S_ + s) * DK_ + dk);
                __half2* p1 = (__half2*)(out + ((size_t)(bi * H_ + hh) * S_ + s + 8) * DK_ + dk);
                *p0 = __floats2half2_rn(v0, v1);
                *p1 = __floats2half2_rn(v2, v3);
            }
        }
    }
}

// grid (8, 32, 4): z in [0,3) = Q/K/V projections; z==3 = mask AND-reduce
__global__ void __launch_bounds__(256) gemm_qkv_kernel(
    const __half* __restrict__ A0, const __half* __restrict__ A1,
    const __half* __restrict__ A2,
    const __half* __restrict__ W0, const __half* __restrict__ W1,
    const __half* __restrict__ W2,
    const float* __restrict__ b0, const float* __restrict__ b1,
    const float* __restrict__ b2,
    __half* __restrict__ o0, __half* __restrict__ o1, __half* __restrict__ o2,
    const int4* __restrict__ mask4)
{
    extern __shared__ __align__(128) char dsm[];
    const int z = blockIdx.z;
    if (z == 3) {
        const int bid = blockIdx.y * 8 + blockIdx.x;      // 0..255
        const int base = bid * 256 + threadIdx.x;         // 0..65535
        int bad = 0;
        #pragma unroll
        for (int j = 0; j < 16; j++) {
            int4 v = mask4[base + j * 65536];
            if (!(v.x && v.y && v.z && v.w)) bad = 1;
        }
        if (bad) g_maskAll = 0;
        return;
    }
    const __half* A = (z == 0) ? A0 : (z == 1) ? A1 : A2;
    const __half* W = (z == 0) ? W0 : (z == 1) ? W1 : W2;
    const float*  b = (z == 0) ? b0 : (z == 1) ? b1 : b2;
    __half*       o = (z == 0) ? o0 : (z == 1) ? o1 : o2;
    gemm_body<0>(A, W, b, o, dsm, blockIdx.y * 128, blockIdx.x * 128);
}

__global__ void __launch_bounds__(256) gemm_o_kernel(
    const __half* __restrict__ A, const __half* __restrict__ W,
    const float* __restrict__ bias, float* __restrict__ out)
{
    extern __shared__ __align__(128) char dsm[];
    gemm_body<2>(A, W, bias, out, dsm, blockIdx.y * 128, blockIdx.x * 128);
}

// ---------------------------------------------------------------------------
// HMMA flash attention (no-max softmax, O in f32 registers).
// CTA = (b, h, 128 q). EIGHT warps x 16 q rows (warp tile 16x64) — doubles
// warps/SMSP vs the 4x32 layout to hide MUFU/LDSM/MMA latency (occ was 11.5%,
// issue 45.8%). Per-thread registers roughly halve. KV tiles of 64,
// 3-stage cp.async pipeline; Q staging region recycled as third KV buffer.
// ---------------------------------------------------------------------------
__global__ void __launch_bounds__(256) attn_mma_kernel(const int* __restrict__ mask)
{
    __shared__ __align__(128) char smem[49152];
    const uint32_t sb = smem_u32(smem);
    const int tid = threadIdx.x, w = tid >> 5, lane = tid & 31;
    const int gid = lane >> 2, tig = lane & 3;
    const int h = blockIdx.y, bi = blockIdx.z;
    const int q0 = blockIdx.x * 128;

    const __half* Qb = g_Qh + ((size_t)(bi * H_ + h) * S_ + q0) * DK_;
    const __half* Kb = g_Kh + (size_t)(bi * H_ + h) * S_ * DK_;
    const __half* Vb = g_Vh + (size_t)(bi * H_ + h) * S_ * DK_;

    const uint32_t roff[3] = {16384u, 32768u, 0u};

    // stage Q (plain LDG/STS; 128 rows x 128B) into region 0
    #pragma unroll
    for (int i = 0; i < 4; i++) {
        int idx = tid + i * 256;
        int r = idx >> 3, ch = idx & 7;
        *(uint4*)(smem + sw128(r, ch)) = *(const uint4*)(Qb + (size_t)r * DK_ + ch * 8);
    }

    auto stage_kv = [&](int kv0, uint32_t off) {
        uint32_t base = sb + off;
        #pragma unroll
        for (int i = 0; i < 2; i++) {
            int idx = tid + i * 256;
            int r = idx >> 3, ch = idx & 7;
            CPA(base + sw128(r, ch), Kb + (size_t)(kv0 + r) * DK_ + ch * 8);
            CPA(base + 8192 + sw128(r, ch), Vb + (size_t)(kv0 + r) * DK_ + ch * 8);
        }
        CPC();
    };
    stage_kv(0, roff[0]);
    stage_kv(64, roff[1]);
    __syncthreads();   // Q visible to all warps

    // Q fragments (16 rows per warp), scaled by 1/8 (exact in f16)
    uint32_t qf[4][4];
    #pragma unroll
    for (int kt = 0; kt < 4; kt++) {
        int r = w * 16 + (lane & 7) + ((lane >> 3) & 1) * 8;
        int ch = kt * 2 + (lane >> 4);
        ldsm4(qf[kt], sb + sw128(r, ch));
        const uint32_t scl = 0x30003000;  // half2(0.125, 0.125)
        #pragma unroll
        for (int e = 0; e < 4; e++)
            asm("mul.rn.f16x2 %0, %0, %1;" : "+r"(qf[kt][e]) : "r"(scl));
    }
    __syncthreads();   // qf done before stage 2 overwrites region 0

    float o[8][4] = {};
    float ps[2] = {};                  // per-thread partial row sums
    const int allm = g_maskAll;

    for (int it = 0; it < S_ / 64; ++it) {
        if (it < S_ / 64 - 1) { CPW(1); } else { CPW(0); }
        __syncthreads();
        if (it + 2 < S_ / 64) stage_kv((it + 2) * 64, roff[(it + 2) % 3]);
        const uint32_t bK = sb + roff[it % 3];
        const uint32_t bV = bK + 8192;

        // S = Q K^T  (m16 x n64 per warp)
        float s[8][4] = {};
        #pragma unroll
        for (int kt = 0; kt < 4; ++kt) {
            uint32_t bk[8][2];
            #pragma unroll
            for (int p = 0; p < 4; p++) {
                int r = p * 16 + (lane & 7) + ((lane >> 4) & 1) * 8;
                int ch = kt * 2 + ((lane >> 3) & 1);
                uint32_t t[4];
                ldsm4(t, bK + sw128(r, ch));
                bk[p * 2][0] = t[0]; bk[p * 2][1] = t[1];
                bk[p * 2 + 1][0] = t[2]; bk[p * 2 + 1][1] = t[3];
            }
            #pragma unroll
            for (int j = 0; j < 8; j++)
                mma16816(s[j], qf[kt], bk[j]);
        }

        if (!allm) {  // general-mask slow path
            const int kv0 = it * 64;
            const int r0 = q0 + w * 16 + gid;
            const int* mr0 = mask + (size_t)r0 * S_;
            const int* mr1 = mask + (size_t)(r0 + 8) * S_;
            #pragma unroll
            for (int j = 0; j < 8; j++) {
                const int c = kv0 + j * 8 + 2 * tig;
                if (!mr0[c])     s[j][0] = -1e9f;
                if (!mr0[c + 1]) s[j][1] = -1e9f;
                if (!mr1[c])     s[j][2] = -1e9f;
                if (!mr1[c + 1]) s[j][3] = -1e9f;
            }
        }

        // P = exp(S) packed as A fragments; row-sum partials accumulate inline
        uint32_t pf[4][4];
        #pragma unroll
        for (int j2 = 0; j2 < 4; j2++) {
            pf[j2][0] = exp_pack_sum(s[2 * j2][0],     s[2 * j2][1],     &ps[0]);
            pf[j2][1] = exp_pack_sum(s[2 * j2][2],     s[2 * j2][3],     &ps[1]);
            pf[j2][2] = exp_pack_sum(s[2 * j2 + 1][0], s[2 * j2 + 1][1], &ps[0]);
            pf[j2][3] = exp_pack_sum(s[2 * j2 + 1][2], s[2 * j2 + 1][3], &ps[1]);
        }

        // O += P @ V   (V consumed via ldmatrix.trans from [kv][dk])
        #pragma unroll
        for (int j2 = 0; j2 < 4; ++j2) {
            uint32_t bv[8][2];
            #pragma unroll
            for (int p = 0; p < 4; p++) {
                int r = j2 * 16 + (lane & 7) + ((lane >> 3) & 1) * 8;
                int ch = p * 2 + (lane >> 4);
                uint32_t t[4];
                ldsm4t(t, bV + sw128(r, ch));
                bv[p * 2][0] = t[0]; bv[p * 2][1] = t[1];
                bv[p * 2 + 1][0] = t[2]; bv[p * 2 + 1][1] = t[3];
            }
            #pragma unroll
            for (int nt = 0; nt < 8; nt++)
                mma16816(o[nt], pf[j2], bv[nt]);
        }
    }

    // quad reduce row sums: lanes gid*4+tig share row gid (and gid+8)
    #pragma unroll
    for (int e = 0; e < 2; e++) {
        float v = ps[e];
        v += __shfl_xor_sync(0xFFFFFFFFu, v, 1);
        v += __shfl_xor_sync(0xFFFFFFFFu, v, 2);
        ps[e] = v;
    }

    // epilogue: divide by row sums, write f16 to g_Xf [b,s,D]
    {
        const float i0 = 1.f / ps[0];
        const float i1 = 1.f / ps[1];
        const int r0 = q0 + w * 16 + gid;
        __half2* X0 = (__half2*)(g_Xf + ((size_t)(bi * S_ + r0)) * D_ + h * DK_);
        __half2* X1 = (__half2*)(g_Xf + ((size_t)(bi * S_ + r0 + 8)) * D_ + h * DK_);
        #pragma unroll
        for (int nt = 0; nt < 8; nt++) {
            X0[nt * 4 + tig] = __floats2half2_rn(o[nt][0] * i0, o[nt][1] * i0);
            X1[nt * 4 + tig] = __floats2half2_rn(o[nt][2] * i1, o[nt][3] * i1);
        }
    }
}

// ---------------------------------------------------------------------------
extern "C" void kernel_launch(void* const* d_in, const int* in_sizes, int n_in,
                              void* d_out, int out_size)
{
    const float* q_in = (const float*)d_in[0];
    const float* k_in = (const float*)d_in[1];
    const float* v_in = (const float*)d_in[2];
    const int*   mask = (const int*)  d_in[3];
    const float* w_q  = (const float*)d_in[4];
    const float* b_q  = (const float*)d_in[5];
    const float* w_k  = (const float*)d_in[6];
    const float* b_k  = (const float*)d_in[7];
    const float* w_v  = (const float*)d_in[8];
    const float* b_v  = (const float*)d_in[9];
    const float* w_o  = (const float*)d_in[10];
    const float* b_o  = (const float*)d_in[11];
    float* out = (float*)d_out;

    __half *pqf, *pkf, *pvf, *pwq, *pwk, *pwv, *pwo, *pQh, *pKh, *pVh, *pXf;
    cudaGetSymbolAddress((void**)&pqf, g_qf);
    cudaGetSymbolAddress((void**)&pkf, g_kf);
    cudaGetSymbolAddress((void**)&pvf, g_vf);
    cudaGetSymbolAddress((void**)&pwq, g_wq);
    cudaGetSymbolAddress((void**)&pwk, g_wk);
    cudaGetSymbolAddress((void**)&pwv, g_wv);
    cudaGetSymbolAddress((void**)&pwo, g_wo);
    cudaGetSymbolAddress((void**)&pQh, g_Qh);
    cudaGetSymbolAddress((void**)&pKh, g_Kh);
    cudaGetSymbolAddress((void**)&pVh, g_Vh);
    cudaGetSymbolAddress((void**)&pXf, g_Xf);

    const int GSMEM = 98304;
    cudaFuncSetAttribute(gemm_qkv_kernel,
                         cudaFuncAttributeMaxDynamicSharedMemorySize, GSMEM);
    cudaFuncSetAttribute(gemm_o_kernel,
                         cudaFuncAttributeMaxDynamicSharedMemorySize, GSMEM);

    const int NA = NTOK * D_;  // 4M elems per activation tensor
    const int NW = D_ * D_;    // 1M elems per weight tensor
    cvtA_kernel<<<dim3(NA / (8 * 256), 3), 256>>>(q_in, k_in, v_in, pqf, pkf, pvf);
    cvtW_kernel<<<dim3(NW / (8 * 256), 4), 256>>>(w_q, w_k, w_v, w_o,
                                                  pwq, pwk, pwv, pwo);

    gemm_qkv_kernel<<<dim3(D_ / 128, NTOK / 128, 4), 256, GSMEM>>>(
        pqf, pkf, pvf, pwq, pwk, pwv, b_q, b_k, b_v, pQh, pKh, pVh,
        (const int4*)mask);

    attn_mma_kernel<<<dim3(S_ / 128, H_, B_), 256>>>(mask);

    gemm_o_kernel<<<dim3(D_ / 128, NTOK / 128), 256, GSMEM>>>(pXf, pwo, b_o, out);
}

// round 17
// speedup vs baseline: 1.0768x; 1.0768x over previous
#include <cuda_runtime.h>
#include <cuda_fp16.h>
#include <cstdint>
#include <math.h>

#define B_ 2
#define S_ 2048
#define D_ 1024
#define H_ 16
#define DK_ 64
#define NTOK (B_*S_)

// ---------------------------------------------------------------------------
// Scratch (device globals — allocation is forbidden)
// ---------------------------------------------------------------------------
__device__ __half g_qf[(size_t)NTOK * D_];
__device__ __half g_kf[(size_t)NTOK * D_];
__device__ __half g_vf[(size_t)NTOK * D_];
__device__ __half g_wq[(size_t)D_ * D_];
__device__ __half g_wk[(size_t)D_ * D_];
__device__ __half g_wv[(size_t)D_ * D_];
__device__ __half g_wo[(size_t)D_ * D_];
__device__ __half g_Qh[(size_t)NTOK * D_];   // [B,H,S,DK]
__device__ __half g_Kh[(size_t)NTOK * D_];   // [B,H,S,DK]
__device__ __half g_Vh[(size_t)NTOK * D_];   // [B,H,S,DK]
__device__ __half g_Xf[(size_t)NTOK * D_];   // [B,S,D]
__device__ int    g_maskAll;

// ---------------------------------------------------------------------------
// Baseline-PTX helpers (no sm_103a-only features)
// ---------------------------------------------------------------------------
__device__ __forceinline__ uint32_t smem_u32(const void* p) {
    uint32_t a;
    asm("{ .reg .u64 t; cvta.to.shared.u64 t, %1; cvt.u32.u64 %0, t; }"
        : "=r"(a) : "l"(p));
    return a;
}

#define CPA(dst, src) \
    asm volatile("cp.async.cg.shared.global [%0], [%1], 16;" \
        :: "r"((uint32_t)(dst)), "l"(src) : "memory")
#define CPC() asm volatile("cp.async.commit_group;" ::: "memory")
#define CPW(N) asm volatile("cp.async.wait_group %0;" :: "n"(N) : "memory")

__device__ __forceinline__ void ldsm4(uint32_t* r, uint32_t a) {
    asm volatile("ldmatrix.sync.aligned.m8n8.x4.shared.b16 {%0,%1,%2,%3}, [%4];"
        : "=r"(r[0]), "=r"(r[1]), "=r"(r[2]), "=r"(r[3]) : "r"(a));
}
__device__ __forceinline__ void ldsm4t(uint32_t* r, uint32_t a) {
    asm volatile("ldmatrix.sync.aligned.m8n8.x4.trans.shared.b16 {%0,%1,%2,%3}, [%4];"
        : "=r"(r[0]), "=r"(r[1]), "=r"(r[2]), "=r"(r[3]) : "r"(a));
}
__device__ __forceinline__ void mma16816(float* d, const uint32_t* a, const uint32_t* b) {
    asm volatile("mma.sync.aligned.m16n8k16.row.col.f32.f16.f16.f32 "
        "{%0,%1,%2,%3}, {%4,%5,%6,%7}, {%8,%9}, {%0,%1,%2,%3};"
        : "+f"(d[0]), "+f"(d[1]), "+f"(d[2]), "+f"(d[3])
        : "r"(a[0]), "r"(a[1]), "r"(a[2]), "r"(a[3]), "r"(b[0]), "r"(b[1]));
}

// exp2 of a pair in f16: pack two f32 (already scaled by log2e) to f16x2,
// then ONE MUFU op computes both lanes. P is f16-bound anyway (MMA operand).
__device__ __forceinline__ uint32_t exp2_pack(float lo, float hi) {
    uint32_t u;
    asm("cvt.rn.f16x2.f32 %0, %1, %2;" : "=r"(u) : "f"(hi), "f"(lo));
    asm("ex2.approx.f16x2 %0, %0;" : "+r"(u));
    return u;
}

// swizzle: 128B rows (8 x 16B chunks)
__device__ __forceinline__ uint32_t sw128(int r, int ch) {
    return (uint32_t)(r * 128 + 16 * (ch ^ (r & 7)));
}

// ---------------------------------------------------------------------------
// fused fp32 -> fp16 conversions (grid.y selects tensor; 8 elems/thread)
// also re-arms g_maskAll (stream-ordered before the mask reduce slice)
// ---------------------------------------------------------------------------
__global__ void __launch_bounds__(256) cvtA_kernel(
    const float* __restrict__ a0, const float* __restrict__ a1,
    const float* __restrict__ a2,
    __half* __restrict__ o0, __half* __restrict__ o1, __half* __restrict__ o2)
{
    if (blockIdx.x == 0 && blockIdx.y == 0 && threadIdx.x == 0) g_maskAll = 1;
    const int z = blockIdx.y;
    const float* in = (z == 0) ? a0 : (z == 1) ? a1 : a2;
    __half* out = (z == 0) ? o0 : (z == 1) ? o1 : o2;
    int i = (blockIdx.x * 256 + threadIdx.x) * 8;
    float4 va = *(const float4*)(in + i);
    float4 vb = *(const float4*)(in + i + 4);
    __half2 h0 = __floats2half2_rn(va.x, va.y);
    __half2 h1 = __floats2half2_rn(va.z, va.w);
    __half2 h2 = __floats2half2_rn(vb.x, vb.y);
    __half2 h3 = __floats2half2_rn(vb.z, vb.w);
    uint4 u;
    u.x = *(uint32_t*)&h0; u.y = *(uint32_t*)&h1;
    u.z = *(uint32_t*)&h2; u.w = *(uint32_t*)&h3;
    *(uint4*)(out + i) = u;
}

__global__ void __launch_bounds__(256) cvtW_kernel(
    const float* __restrict__ a0, const float* __restrict__ a1,
    const float* __restrict__ a2, const float* __restrict__ a3,
    __half* __restrict__ o0, __half* __restrict__ o1,
    __half* __restrict__ o2, __half* __restrict__ o3)
{
    const int z = blockIdx.y;
    const float* in = (z == 0) ? a0 : (z == 1) ? a1 : (z == 2) ? a2 : a3;
    __half* out = (z == 0) ? o0 : (z == 1) ? o1 : (z == 2) ? o2 : o3;
    int i = (blockIdx.x * 256 + threadIdx.x) * 8;
    float4 va = *(const float4*)(in + i);
    float4 vb = *(const float4*)(in + i + 4);
    __half2 h0 = __floats2half2_rn(va.x, va.y);
    __half2 h1 = __floats2half2_rn(va.z, va.w);
    __half2 h2 = __floats2half2_rn(vb.x, vb.y);
    __half2 h3 = __floats2half2_rn(vb.z, vb.w);
    uint4 u;
    u.x = *(uint32_t*)&h0; u.y = *(uint32_t*)&h1;
    u.z = *(uint32_t*)&h2; u.w = *(uint32_t*)&h3;
    *(uint4*)(out + i) = u;
}

// ---------------------------------------------------------------------------
// HMMA GEMM body: C[m,n] = sum_k A[m,k]*W[n,k] + bias[n]
// CTA tile 128x128, 256 thr = 8 warps (2m x 4n), warp tile 64x32, k-chunk 64.
// 3-stage cp.async pipeline (3 x 32KB = 96KB DYNAMIC smem), 1 barrier/iter.
// EPI: 0 = f16 scattered to [B,H,S,DK]; 2 = f32 flat [M,D]
// ---------------------------------------------------------------------------
template<int EPI>
__device__ __forceinline__ void gemm_body(
    const __half* __restrict__ A, const __half* __restrict__ W,
    const float* __restrict__ bias, void* __restrict__ outp,
    char* smem, int m0, int n0)
{
    const uint32_t sb = smem_u32(smem);
    const int tid = threadIdx.x, wid = tid >> 5, lane = tid & 31;
    const int gid = lane >> 2, tig = lane & 3;
    const int wm = wid >> 2, wn = wid & 3;

    // staging: 128 rows x 128B per operand per stage; 4 chunks/thread/operand
    auto stage = [&](int kc, int reg) {
        const uint32_t base = sb + reg * 32768;
        #pragma unroll
        for (int i = 0; i < 4; i++) {
            int idx = tid + i * 256;           // 0..1023
            int r = idx >> 3, ch = idx & 7;
            CPA(base + sw128(r, ch),
                A + (size_t)(m0 + r) * D_ + kc * 64 + ch * 8);
            CPA(base + 16384 + sw128(r, ch),
                W + (size_t)(n0 + r) * D_ + kc * 64 + ch * 8);
        }
        CPC();
    };

    stage(0, 0);
    stage(1, 1);
    float acc[4][4][4] = {};

    for (int kc = 0; kc < 16; ++kc) {
        if (kc < 15) { CPW(1); } else { CPW(0); }
        __syncthreads();
        if (kc + 2 < 16) stage(kc + 2, (kc + 2) % 3);
        const uint32_t base = sb + (kc % 3) * 32768;

        #pragma unroll
        for (int kt = 0; kt < 4; ++kt) {
            uint32_t af[4][4];
            #pragma unroll
            for (int mt = 0; mt < 4; mt++) {
                int r = wm * 64 + mt * 16 + (lane & 7) + ((lane >> 3) & 1) * 8;
                int ch = kt * 2 + (lane >> 4);
                ldsm4(af[mt], base + sw128(r, ch));
            }
            uint32_t bf[4][2];
            #pragma unroll
            for (int p = 0; p < 2; p++) {
                int r = wn * 32 + p * 16 + (lane & 7) + ((lane >> 4) & 1) * 8;
                int ch = kt * 2 + ((lane >> 3) & 1);
                uint32_t t[4];
                ldsm4(t, base + 16384 + sw128(r, ch));
                bf[p * 2][0] = t[0]; bf[p * 2][1] = t[1];
                bf[p * 2 + 1][0] = t[2]; bf[p * 2 + 1][1] = t[3];
            }
            #pragma unroll
            for (int mt = 0; mt < 4; mt++)
                #pragma unroll
                for (int nt = 0; nt < 4; nt++)
                    mma16816(acc[mt][nt], af[mt], bf[nt]);
        }
    }

    // epilogue
    #pragma unroll
    for (int mt = 0; mt < 4; mt++) {
        #pragma unroll
        for (int nt = 0; nt < 4; nt++) {
            const int row0 = m0 + wm * 64 + mt * 16 + gid;
            const int col  = n0 + wn * 32 + nt * 8 + 2 * tig;
            const float b0 = __ldg(bias + col), b1 = __ldg(bias + col + 1);
            const float v0 = acc[mt][nt][0] + b0, v1 = acc[mt][nt][1] + b1;
            const float v2 = acc[mt][nt][2] + b0, v3 = acc[mt][nt][3] + b1;
            if (EPI == 2) {
                float* out = (float*)outp;
                *(float2*)(out + (size_t)row0 * D_ + col)       = make_float2(v0, v1);
                *(float2*)(out + (size_t)(row0 + 8) * D_ + col) = make_float2(v2, v3);
            } else {
                __half* out = (__half*)outp;
                const int bi = row0 >> 11, s = row0 & (S_ - 1);
                const int hh = col >> 6, dk = col & 63;
                __half2* p0 = (__half2*)(out + ((size_t)(bi * H_ + hh) * S_ + s) * DK_ + dk);
                __half2* p1 = (__half2*)(out + ((size_t)(bi * H_ + hh) * S_ + s + 8) * DK_ + dk);
                *p0 = __floats2half2_rn(v0, v1);
                *p1 = __floats2half2_rn(v2, v3);
            }
        }
    }
}

// grid (8, 32, 4): z in [0,3) = Q/K/V projections; z==3 = mask AND-reduce
__global__ void __launch_bounds__(256) gemm_qkv_kernel(
    const __half* __restrict__ A0, const __half* __restrict__ A1,
    const __half* __restrict__ A2,
    const __half* __restrict__ W0, const __half* __restrict__ W1,
    const __half* __restrict__ W2,
    const float* __restrict__ b0, const float* __restrict__ b1,
    const float* __restrict__ b2,
    __half* __restrict__ o0, __half* __restrict__ o1, __half* __restrict__ o2,
    const int4* __restrict__ mask4)
{
    extern __shared__ __align__(128) char dsm[];
    const int z = blockIdx.z;
    if (z == 3) {
        const int bid = blockIdx.y * 8 + blockIdx.x;      // 0..255
        const int base = bid * 256 + threadIdx.x;         // 0..65535
        int bad = 0;
        #pragma unroll
        for (int j = 0; j < 16; j++) {
            int4 v = mask4[base + j * 65536];
            if (!(v.x && v.y && v.z && v.w)) bad = 1;
        }
        if (bad) g_maskAll = 0;
        return;
    }
    const __half* A = (z == 0) ? A0 : (z == 1) ? A1 : A2;
    const __half* W = (z == 0) ? W0 : (z == 1) ? W1 : W2;
    const float*  b = (z == 0) ? b0 : (z == 1) ? b1 : b2;
    __half*       o = (z == 0) ? o0 : (z == 1) ? o1 : o2;
    gemm_body<0>(A, W, b, o, dsm, blockIdx.y * 128, blockIdx.x * 128);
}

__global__ void __launch_bounds__(256) gemm_o_kernel(
    const __half* __restrict__ A, const __half* __restrict__ W,
    const float* __restrict__ bias, float* __restrict__ out)
{
    extern __shared__ __align__(128) char dsm[];
    gemm_body<2>(A, W, bias, out, dsm, blockIdx.y * 128, blockIdx.x * 128);
}

// ---------------------------------------------------------------------------
// HMMA flash attention (no-max softmax, O in f32 registers).
// CTA = (b, h, 128 q). FOUR warps x 32 q (R15 layout — best measured; the
// 8-warp variant doubled LDSM work and regressed). KV tiles of 64, 3-stage
// cp.async pipeline; Q staging region recycled as third KV buffer.
// exp path: scores scaled by log2e in f32 (fma pipe), ONE ex2.approx.f16x2
// per value-pair (MUFU halved vs __expf). Row sums via P @ ones MMA (fp32
// exact over the same rounded P used for P@V).
// ---------------------------------------------------------------------------
__global__ void __launch_bounds__(128) attn_mma_kernel(const int* __restrict__ mask)
{
    __shared__ __align__(128) char smem[49152];
    const uint32_t sb = smem_u32(smem);
    const int tid = threadIdx.x, w = tid >> 5, lane = tid & 31;
    const int gid = lane >> 2, tig = lane & 3;
    const int h = blockIdx.y, bi = blockIdx.z;
    const int q0 = blockIdx.x * 128;

    const __half* Qb = g_Qh + ((size_t)(bi * H_ + h) * S_ + q0) * DK_;
    const __half* Kb = g_Kh + (size_t)(bi * H_ + h) * S_ * DK_;
    const __half* Vb = g_Vh + (size_t)(bi * H_ + h) * S_ * DK_;

    const uint32_t roff[3] = {16384u, 32768u, 0u};

    // stage Q (plain LDG/STS; 128 rows x 128B) into region 0
    #pragma unroll
    for (int i = 0; i < 8; i++) {
        int idx = tid + i * 128;
        int r = idx >> 3, ch = idx & 7;
        *(uint4*)(smem + sw128(r, ch)) = *(const uint4*)(Qb + (size_t)r * DK_ + ch * 8);
    }

    auto stage_kv = [&](int kv0, uint32_t off) {
        uint32_t base = sb + off;
        #pragma unroll
        for (int i = 0; i < 4; i++) {
            int idx = tid + i * 128;
            int r = idx >> 3, ch = idx & 7;
            CPA(base + sw128(r, ch), Kb + (size_t)(kv0 + r) * DK_ + ch * 8);
            CPA(base + 8192 + sw128(r, ch), Vb + (size_t)(kv0 + r) * DK_ + ch * 8);
        }
        CPC();
    };
    stage_kv(0, roff[0]);
    stage_kv(64, roff[1]);
    __syncthreads();   // Q visible to all warps

    // Q fragments in registers, scaled by 1/8 (exact in f16)
    uint32_t qf[2][4][4];
    #pragma unroll
    for (int mt = 0; mt < 2; mt++)
        #pragma unroll
        for (int kt = 0; kt < 4; kt++) {
            int r = w * 32 + mt * 16 + (lane & 7) + ((lane >> 3) & 1) * 8;
            int ch = kt * 2 + (lane >> 4);
            ldsm4(qf[mt][kt], sb + sw128(r, ch));
            const uint32_t scl = 0x30003000;  // half2(0.125, 0.125)
            #pragma unroll
            for (int e = 0; e < 4; e++)
                asm("mul.rn.f16x2 %0, %0, %1;" : "+r"(qf[mt][kt][e]) : "r"(scl));
        }
    __syncthreads();   // qf done before stage 2 overwrites region 0

    float o[2][8][4] = {};
    float rs[2][4] = {};
    const uint32_t bon[2] = {0x3C003C00u, 0x3C003C00u};  // ones B fragment
    const float L2E = 1.4426950408889634f;
    const int allm = g_maskAll;

    for (int it = 0; it < S_ / 64; ++it) {
        if (it < S_ / 64 - 1) { CPW(1); } else { CPW(0); }
        __syncthreads();
        if (it + 2 < S_ / 64) stage_kv((it + 2) * 64, roff[(it + 2) % 3]);
        const uint32_t bK = sb + roff[it % 3];
        const uint32_t bV = bK + 8192;

        // S = Q K^T  (m32 x n64 per warp)
        float s[2][8][4] = {};
        #pragma unroll
        for (int kt = 0; kt < 4; ++kt) {
            uint32_t bk[8][2];
            #pragma unroll
            for (int p = 0; p < 4; p++) {
                int r = p * 16 + (lane & 7) + ((lane >> 4) & 1) * 8;
                int ch = kt * 2 + ((lane >> 3) & 1);
                uint32_t t[4];
                ldsm4(t, bK + sw128(r, ch));
                bk[p * 2][0] = t[0]; bk[p * 2][1] = t[1];
                bk[p * 2 + 1][0] = t[2]; bk[p * 2 + 1][1] = t[3];
            }
            #pragma unroll
            for (int mt = 0; mt < 2; mt++)
                #pragma unroll
                for (int j = 0; j < 8; j++)
                    mma16816(s[mt][j], qf[mt][kt], bk[j]);
        }

        if (!allm) {  // general-mask slow path
            const int kv0 = it * 64;
            #pragma unroll
            for (int mt = 0; mt < 2; mt++) {
                const int r0 = q0 + w * 32 + mt * 16 + gid;
                const int* mr0 = mask + (size_t)r0 * S_;
                const int* mr1 = mask + (size_t)(r0 + 8) * S_;
                #pragma unroll
                for (int j = 0; j < 8; j++) {
                    const int c = kv0 + j * 8 + 2 * tig;
                    if (!mr0[c])     s[mt][j][0] = -1e9f;
                    if (!mr0[c + 1]) s[mt][j][1] = -1e9f;
                    if (!mr1[c])     s[mt][j][2] = -1e9f;
                    if (!mr1[c + 1]) s[mt][j][3] = -1e9f;
                }
            }
        }
        // (masked: -1e9*L2E -> f16 -inf -> ex2 -> exactly 0)

        // P = 2^(S*log2e) in f16x2 (one MUFU per pair)
        uint32_t pf[2][4][4];
        #pragma unroll
        for (int mt = 0; mt < 2; mt++)
            #pragma unroll
            for (int j2 = 0; j2 < 4; j2++) {
                pf[mt][j2][0] = exp2_pack(s[mt][2 * j2][0] * L2E,     s[mt][2 * j2][1] * L2E);
                pf[mt][j2][1] = exp2_pack(s[mt][2 * j2][2] * L2E,     s[mt][2 * j2][3] * L2E);
                pf[mt][j2][2] = exp2_pack(s[mt][2 * j2 + 1][0] * L2E, s[mt][2 * j2 + 1][1] * L2E);
                pf[mt][j2][3] = exp2_pack(s[mt][2 * j2 + 1][2] * L2E, s[mt][2 * j2 + 1][3] * L2E);
            }

        // row sums: P @ ones (fp32-exact over the rounded P)
        #pragma unroll
        for (int mt = 0; mt < 2; mt++)
            #pragma unroll
            for (int j2 = 0; j2 < 4; j2++)
                mma16816(rs[mt], pf[mt][j2], bon);

        // O += P @ V   (V consumed via ldmatrix.trans from [kv][dk])
        #pragma unroll
        for (int j2 = 0; j2 < 4; ++j2) {
            uint32_t bv[8][2];
            #pragma unroll
            for (int p = 0; p < 4; p++) {
                int r = j2 * 16 + (lane & 7) + ((lane >> 3) & 1) * 8;
                int ch = p * 2 + (lane >> 4);
                uint32_t t[4];
                ldsm4t(t, bV + sw128(r, ch));
                bv[p * 2][0] = t[0]; bv[p * 2][1] = t[1];
                bv[p * 2 + 1][0] = t[2]; bv[p * 2 + 1][1] = t[3];
            }
            #pragma unroll
            for (int mt = 0; mt < 2; mt++)
                #pragma unroll
                for (int nt = 0; nt < 8; nt++)
                    mma16816(o[mt][nt], pf[mt][j2], bv[nt]);
        }
    }

    // epilogue: divide by row sums, write f16 to g_Xf [b,s,D]
    #pragma unroll
    for (int mt = 0; mt < 2; mt++) {
        const float i0 = 1.f / rs[mt][0];
        const float i1 = 1.f / rs[mt][2];
        const int r0 = q0 + w * 32 + mt * 16 + gid;
        __half2* X0 = (__half2*)(g_Xf + ((size_t)(bi * S_ + r0)) * D_ + h * DK_);
        __half2* X1 = (__half2*)(g_Xf + ((size_t)(bi * S_ + r0 + 8)) * D_ + h * DK_);
        #pragma unroll
        for (int nt = 0; nt < 8; nt++) {
            X0[nt * 4 + tig] = __floats2half2_rn(o[mt][nt][0] * i0, o[mt][nt][1] * i0);
            X1[nt * 4 + tig] = __floats2half2_rn(o[mt][nt][2] * i1, o[mt][nt][3] * i1);
        }
    }
}

// ---------------------------------------------------------------------------
extern "C" void kernel_launch(void* const* d_in, const int* in_sizes, int n_in,
                              void* d_out, int out_size)
{
    const float* q_in = (const float*)d_in[0];
    const float* k_in = (const float*)d_in[1];
    const float* v_in = (const float*)d_in[2];
    const int*   mask = (const int*)  d_in[3];
    const float* w_q  = (const float*)d_in[4];
    const float* b_q  = (const float*)d_in[5];
    const float* w_k  = (const float*)d_in[6];
    const float* b_k  = (const float*)d_in[7];
    const float* w_v  = (const float*)d_in[8];
    const float* b_v  = (const float*)d_in[9];
    const float* w_o  = (const float*)d_in[10];
    const float* b_o  = (const float*)d_in[11];
    float* out = (float*)d_out;

    __half *pqf, *pkf, *pvf, *pwq, *pwk, *pwv, *pwo, *pQh, *pKh, *pVh, *pXf;
    cudaGetSymbolAddress((void**)&pqf, g_qf);
    cudaGetSymbolAddress((void**)&pkf, g_kf);
    cudaGetSymbolAddress((void**)&pvf, g_vf);
    cudaGetSymbolAddress((void**)&pwq, g_wq);
    cudaGetSymbolAddress((void**)&pwk, g_wk);
    cudaGetSymbolAddress((void**)&pwv, g_wv);
    cudaGetSymbolAddress((void**)&pwo, g_wo);
    cudaGetSymbolAddress((void**)&pQh, g_Qh);
    cudaGetSymbolAddress((void**)&pKh, g_Kh);
    cudaGetSymbolAddress((void**)&pVh, g_Vh);
    cudaGetSymbolAddress((void**)&pXf, g_Xf);

    const int GSMEM = 98304;
    cudaFuncSetAttribute(gemm_qkv_kernel,
                         cudaFuncAttributeMaxDynamicSharedMemorySize, GSMEM);
    cudaFuncSetAttribute(gemm_o_kernel,
                         cudaFuncAttributeMaxDynamicSharedMemorySize, GSMEM);

    const int NA = NTOK * D_;  // 4M elems per activation tensor
    const int NW = D_ * D_;    // 1M elems per weight tensor
    cvtA_kernel<<<dim3(NA / (8 * 256), 3), 256>>>(q_in, k_in, v_in, pqf, pkf, pvf);
    cvtW_kernel<<<dim3(NW / (8 * 256), 4), 256>>>(w_q, w_k, w_v, w_o,
                                                  pwq, pwk, pwv, pwo);

    gemm_qkv_kernel<<<dim3(D_ / 128, NTOK / 128, 4), 256, GSMEM>>>(
        pqf, pkf, pvf, pwq, pwk, pwv, b_q, b_k, b_v, pQh, pKh, pVh,
        (const int4*)mask);

    attn_mma_kernel<<<dim3(S_ / 128, H_, B_), 128>>>(mask);

    gemm_o_kernel<<<dim3(D_ / 128, NTOK / 128), 256, GSMEM>>>(pXf, pwo, b_o, out);
}